// round 7
// baseline (speedup 1.0000x reference)
#include <cuda_runtime.h>

// HIRNNLayer: 4096 independent nonlinear 2-state recurrences, T=1024.
// One lane per sequence, one warp per 32 sequences. R5's minimized step math
// (chain FFMA->ex2->FFMA->FMNMX; GW = single FFMA) PLUS warp-cooperative
// coalesced global I/O via padded shared memory: per-LDG line count 32 -> 2,
// per-STG 32 -> 1, removing the L1tex wavefront bottleneck that held R4/R5
// at ~37us. Q emitted in-loop (position t uses entering state == rolled
// outs[t-1]); position 0 overwritten post-loop with FINAL-state fluxes
// (jnp.roll is circular).

#define T_LEN 1024
#define CH    32            // steps per chunk
#define NCH   (T_LEN / CH)  // 32 chunks

__device__ __forceinline__ float ex2f(float x) {
    float y;
    asm("ex2.approx.ftz.f32 %0, %1;" : "=f"(y) : "f"(x));
    return y;
}

struct P {
    float insc, smsc, subs, craks, tenr, reck, omr, c1, lg2c;
};

// Validated algebraic step (rel_err ~2e-7 vs reference):
//  - Prec,PET >= 0 => interception maxes dead.
//  - t12 in [0,1] => s = min(fma(t12,INR,pre), fma(t12,cap,pre)).
//  - S' = min(s,SMSC) >= 0 automatically (ETS <= 0.2*S).
//  - GW >= 0 invariant => BAS = reck*GW, GW' = (1-reck)*GW + inj;
//    +/-1e5 clips provably dead.
__device__ __forceinline__ float step(float Prec, float PET,
                                      float& SMS, float& GW, const P& p) {
    float S = SMS;
    // carried chain: FFMA -> ex2 -> FFMA -> FMNMX
    float e   = fmaf(p.c1, S, p.lg2c);
    float cap = ex2f(e);                 // COEFF * exp(-SQ*S/SMSC)
    // ex2 shadow
    float INT = fminf(fminf(p.insc, PET), Prec);
    float INR = Prec - INT;
    float POT = PET - INT;
    float u1  = fmaf(-p.subs,  S, 1.f);
    float v1  = fmaf(-p.craks, S, 1.f);
    float t12 = u1 * v1;
    float w   = u1 - t12;
    float ETS = fminf(POT, p.tenr * S);
    float pre = S - ETS;
    float s_a = fmaf(t12, INR, pre);
    float K   = fminf(s_a, p.smsc);
    // chain tail
    float s_b = fmaf(t12, cap, pre);
    float Sn  = fminf(s_b, K);
    SMS = Sn;
    // GW / Q (off critical path)
    float RMO = fminf(INR, cap);
    float DR  = fmaf(-u1, RMO, INR);     // IRUN + SRUN
    float st  = fminf(s_a, s_b);
    float ov  = st - Sn;                 // overflow recharge
    float inj = fmaf(w, RMO, ov);        // REC + ov
    float BAS = p.reck * GW;
    float Q   = DR + BAS;
    GW = fmaf(p.omr, GW, inj);
    return Q;
}

__global__ void __launch_bounds__(32, 1)
hirnn_kernel(const float* __restrict__ inp,
             const float* __restrict__ pINSC, const float* __restrict__ pCOEFF,
             const float* __restrict__ pSQ,   const float* __restrict__ pSMSC,
             const float* __restrict__ pSUB,  const float* __restrict__ pCRAK,
             const float* __restrict__ pRecK,
             float* __restrict__ out, int B) {
    // padded smem: float2 stride 33 (input), float stride 33 (Q)
    __shared__ float2 sIn[2][32 * 33];
    __shared__ float  sQ[32 * 33];

    int lane = threadIdx.x;
    int b0   = blockIdx.x * 32;
    if (b0 >= B) return;

    float insc  = fminf(fmaxf(pINSC[0] * 5.0f, 0.5f), 5.0f);
    float coeff = fminf(fmaxf(pCOEFF[0] * 400.0f, 50.0f), 400.0f);
    float sq    = fminf(fmaxf(pSQ[0] * 6.0f, 0.0f), 6.0f);
    float smsc  = fminf(fmaxf(pSMSC[0] * 500.0f, 50.0f), 500.0f);
    float sub   = fminf(fmaxf(pSUB[0], 0.0f), 1.0f);
    float crak  = fminf(fmaxf(pCRAK[0], 0.0f), 1.0f);
    float reck  = fminf(fmaxf(pRecK[0] * 0.3f, 0.003f), 0.3f);

    P p;
    float inv = 1.0f / smsc;
    p.insc = insc;  p.smsc = smsc;
    p.subs = sub * inv;  p.craks = crak * inv;  p.tenr = 10.0f * inv;
    p.reck = reck;  p.omr = 1.0f - reck;
    p.c1   = -sq * inv * 1.4426950408889634f;
    p.lg2c = log2f(coeff);

    const float2* x2 = reinterpret_cast<const float2*>(inp);

    // prologue: cooperative coalesced load of chunk 0
    float2 stage[32];
#pragma unroll
    for (int s = 0; s < 32; s++)
        stage[s] = x2[(size_t)(b0 + s) * T_LEN + lane];   // 2 lines/LDG
#pragma unroll
    for (int s = 0; s < 32; s++)
        sIn[0][s * 33 + lane] = stage[s];
    __syncwarp();

    float2 x0 = sIn[0][lane * 33];   // t=0 of own sequence (for the roll fixup)

    float SMS = 0.0f, GW = 0.0f;

    for (int c = 0; c < NCH; c++) {
        int cur = c & 1;

        // issue coalesced LDGs for chunk c+1 (data lands during compute)
        if (c + 1 < NCH) {
#pragma unroll
            for (int s = 0; s < 32; s++)
                stage[s] = x2[(size_t)(b0 + s) * T_LEN + (c + 1) * CH + lane];
        }

        // compute chunk c from smem; stage Q in smem (conflict-free STS.32)
#pragma unroll
        for (int j = 0; j < CH; j++) {
            float2 x = sIn[cur][lane * 33 + j];
            sQ[lane * 33 + j] = step(x.x, x.y, SMS, GW, p);
        }

        // commit staged inputs for chunk c+1 (LDG latency long since covered)
        if (c + 1 < NCH) {
#pragma unroll
            for (int s = 0; s < 32; s++)
                sIn[cur ^ 1][s * 33 + lane] = stage[s];
        }
        __syncwarp();

        // cooperative coalesced store of Q chunk c (1 line/STG.32)
#pragma unroll
        for (int s = 0; s < 32; s++)
            out[(size_t)(b0 + s) * T_LEN + c * CH + lane] = sQ[s * 33 + lane];
        __syncwarp();
    }

    // position 0 <- flux eval with FINAL state (circular roll), state discarded
    float fS = SMS, fG = GW;
    float Q0 = step(x0.x, x0.y, fS, fG, p);
    out[(size_t)(b0 + lane) * T_LEN] = Q0;
}

extern "C" void kernel_launch(void* const* d_in, const int* in_sizes, int n_in,
                              void* d_out, int out_size) {
    const float* inp = (const float*)d_in[0];
    int B = in_sizes[0] / (2 * T_LEN);

    hirnn_kernel<<<(B + 31) / 32, 32>>>(
        inp,
        (const float*)d_in[1], (const float*)d_in[2], (const float*)d_in[3],
        (const float*)d_in[4], (const float*)d_in[5], (const float*)d_in[6],
        (const float*)d_in[7],
        (float*)d_out, B);
}

// round 8
// speedup vs baseline: 1.6036x; 1.6036x over previous
#include <cuda_runtime.h>

// HIRNNLayer: 4096 independent nonlinear 2-state recurrences, T=1024.
// One thread/sequence, single-warp-per-SMSP latency bound. Design:
//  - Phase-split chunks of 16: serial SMS recurrence first (18 instr/step vs
//    ~30-cyc chain), depositing (DR, inj) in registers; then the GW pass
//    (linear recurrence, 2 FFMA/step) + coalesced-per-thread float4 stores.
//  - Direct float4 gmem loads, double-buffered distance-1 prefetch
//    (no smem: R6 showed the smem staging is a net loss).
//  - ~130 regs so ptxas can pack shadow work into chain bubbles (R5's 254
//    regs defeated scheduling).
// Q emitted in-loop (position t uses entering state == rolled outs[t-1]);
// position 0 overwritten post-loop with FINAL-state fluxes (circular roll).

#define T_LEN 1024
#define CH    16
#define NCH   (T_LEN / CH)

__device__ __forceinline__ float ex2f(float x) {
    float y;
    asm("ex2.approx.ftz.f32 %0, %1;" : "=f"(y) : "f"(x));
    return y;
}

struct P {
    float insc, smsc, subs, craks, omt, reck, omr, c1, lg2c;
};

// Serial part of one step (validated algebra, rel_err ~2e-7):
//  - Prec,PET >= 0 => interception maxes dead.
//  - t12 in [0,1] => s = min(fma(t12,INR,pre), fma(t12,cap,pre)).
//  - pre = S - min(POT, tenr*S) = max(S-POT, (1-tenr)*S).
//  - S' = min(s, SMSC) >= 0 automatically (ETS <= 0.2*S).
// Deposits: DR = IRUN+SRUN = INR - u1*RMO;  inj = RECnew = w*RMO + overflow.
__device__ __forceinline__ void step_s(float Prec, float PET, float& SMS,
                                       float& DR, float& inj, const P& p) {
    float S = SMS;
    // carried chain: FFMA -> ex2 -> FFMA -> FMNMX
    float e   = fmaf(p.c1, S, p.lg2c);
    float cap = ex2f(e);                    // COEFF * exp(-SQ*S/SMSC)
    // shadow (input + S dependent, fills the ex2 window)
    float INT = fminf(fminf(p.insc, PET), Prec);
    float INR = Prec - INT;
    float POT = PET - INT;
    float u1  = fmaf(-p.subs,  S, 1.f);
    float v1  = fmaf(-p.craks, S, 1.f);
    float t12 = u1 * v1;
    float w   = u1 - t12;
    float pre = fmaxf(S - POT, p.omt * S);  // S - ETS
    float s_a = fmaf(t12, INR, pre);
    float K   = fminf(s_a, p.smsc);
    // chain tail
    float s_b = fmaf(t12, cap, pre);
    float Sn  = fminf(s_b, K);
    SMS = Sn;
    // deposits (off the carried chain)
    float RMO = fminf(INR, cap);
    DR  = fmaf(-u1, RMO, INR);
    float st  = fminf(s_a, s_b);
    inj = fmaf(w, RMO, st - Sn);            // REC + overflow recharge
}

// One 16-step chunk: 8 input float4 -> serial SMS pass -> GW pass -> 4 stores.
__device__ __forceinline__ void process16(const float4* buf, float4* dst,
                                          float& SMS, float& GW, const P& p) {
    float DR[CH], inj[CH];
#pragma unroll
    for (int j = 0; j < 8; j++) {
        float4 a = buf[j];
        step_s(a.x, a.y, SMS, DR[2 * j],     inj[2 * j],     p);
        step_s(a.z, a.w, SMS, DR[2 * j + 1], inj[2 * j + 1], p);
    }
    // GW pass: linear recurrence, 2 FFMA/step
#pragma unroll
    for (int j = 0; j < 4; j++) {
        float4 q;
        q.x = fmaf(p.reck, GW, DR[4 * j]);     GW = fmaf(p.omr, GW, inj[4 * j]);
        q.y = fmaf(p.reck, GW, DR[4 * j + 1]); GW = fmaf(p.omr, GW, inj[4 * j + 1]);
        q.z = fmaf(p.reck, GW, DR[4 * j + 2]); GW = fmaf(p.omr, GW, inj[4 * j + 2]);
        q.w = fmaf(p.reck, GW, DR[4 * j + 3]); GW = fmaf(p.omr, GW, inj[4 * j + 3]);
        dst[j] = q;
    }
}

__global__ void __launch_bounds__(32, 1)
hirnn_kernel(const float* __restrict__ inp,
             const float* __restrict__ pINSC, const float* __restrict__ pCOEFF,
             const float* __restrict__ pSQ,   const float* __restrict__ pSMSC,
             const float* __restrict__ pSUB,  const float* __restrict__ pCRAK,
             const float* __restrict__ pRecK,
             float* __restrict__ out, int B) {
    int b = blockIdx.x * blockDim.x + threadIdx.x;
    if (b >= B) return;

    float insc  = fminf(fmaxf(pINSC[0] * 5.0f, 0.5f), 5.0f);
    float coeff = fminf(fmaxf(pCOEFF[0] * 400.0f, 50.0f), 400.0f);
    float sq    = fminf(fmaxf(pSQ[0] * 6.0f, 0.0f), 6.0f);
    float smsc  = fminf(fmaxf(pSMSC[0] * 500.0f, 50.0f), 500.0f);
    float sub   = fminf(fmaxf(pSUB[0], 0.0f), 1.0f);
    float crak  = fminf(fmaxf(pCRAK[0], 0.0f), 1.0f);
    float reck  = fminf(fmaxf(pRecK[0] * 0.3f, 0.003f), 0.3f);

    P p;
    float inv = 1.0f / smsc;
    p.insc  = insc;
    p.smsc  = smsc;
    p.subs  = sub * inv;
    p.craks = crak * inv;
    p.omt   = 1.0f - 10.0f * inv;     // 1 - tenr
    p.reck  = reck;
    p.omr   = 1.0f - reck;
    p.c1    = -sq * inv * 1.4426950408889634f;
    p.lg2c  = log2f(coeff);

    const float4* xp4 = reinterpret_cast<const float4*>(inp) + (size_t)b * 512;
    float4*       op4 = reinterpret_cast<float4*>(out) + (size_t)b * 256;

    float4 A[8], Bb[8];
#pragma unroll
    for (int i = 0; i < 8; i++) A[i] = xp4[i];   // chunk 0
    float x0P = A[0].x, x0E = A[0].y;

    float SMS = 0.0f, GW = 0.0f;

    // 64 chunks of 16, double-buffered distance-1 prefetch (~560 cyc cover).
    for (int c = 0; c < NCH; c += 2) {
#pragma unroll
        for (int i = 0; i < 8; i++) Bb[i] = xp4[(c + 1) * 8 + i];
        process16(A, op4 + c * 4, SMS, GW, p);
        if (c + 2 < NCH) {
#pragma unroll
            for (int i = 0; i < 8; i++) A[i] = xp4[(c + 2) * 8 + i];
        }
        process16(Bb, op4 + (c + 1) * 4, SMS, GW, p);
    }

    // position 0 <- flux eval with FINAL state (circular roll)
    {
        float fS = SMS, dr, in_;
        step_s(x0P, x0E, fS, dr, in_, p);
        out[(size_t)b * T_LEN] = fmaf(p.reck, GW, dr);
    }
}

extern "C" void kernel_launch(void* const* d_in, const int* in_sizes, int n_in,
                              void* d_out, int out_size) {
    const float* inp = (const float*)d_in[0];
    int B = in_sizes[0] / (2 * T_LEN);

    hirnn_kernel<<<(B + 31) / 32, 32>>>(
        inp,
        (const float*)d_in[1], (const float*)d_in[2], (const float*)d_in[3],
        (const float*)d_in[4], (const float*)d_in[5], (const float*)d_in[6],
        (const float*)d_in[7],
        (float*)d_out, B);
}